// round 4
// baseline (speedup 1.0000x reference)
#include <cuda_runtime.h>
#include <math.h>

#define L_SEQ 2048
#define B_SZ  16
#define H_DIM 512
#define NS    32
#define BH    (B_SZ*H_DIM)          // 8192
#define LBH   (L_SEQ*B_SZ*H_DIM)    // 16777216

// Scratch (static device globals; no allocations)
__device__ float g_un[LBH];   // normalized input, (L,B,H) layout
__device__ float g_y[LBH];    // post conv+Dskip+gelu, (B,H,L) layout
__device__ float g_rr[H_DIM*NS], g_ri[H_DIM*NS], g_cr[H_DIM*NS], g_ci[H_DIM*NS];

// ---------------------------------------------------------------------------
// K0: per-(h,n) SSM constants:  r = exp(dt*A),  c = 2*C*(r-1)/A  (split re/im)
// ---------------------------------------------------------------------------
__global__ void const_kernel(const float* __restrict__ log_dt,
                             const float* __restrict__ C,
                             const float* __restrict__ log_A_real,
                             const float* __restrict__ A_imag) {
    int idx = blockIdx.x*blockDim.x + threadIdx.x;
    if (idx >= H_DIM*NS) return;
    int h = idx >> 5;
    float dt  = expf(log_dt[h]);
    float Are = -expf(log_A_real[idx]);
    float Aim = A_imag[idx];
    float dre = Are*dt, dim = Aim*dt;
    float er  = expf(dre);
    float rr  = er*cosf(dim), ri = er*sinf(dim);
    // (r - 1) / A
    float nre = rr - 1.f, nim = ri;
    float den = Are*Are + Aim*Aim;
    float qre = (nre*Are + nim*Aim)/den;
    float qim = (nim*Are - nre*Aim)/den;
    float Cre = C[2*idx], Cim = C[2*idx+1];
    float cmre = Cre*qre - Cim*qim;
    float cmim = Cre*qim + Cim*qre;
    g_rr[idx] = rr;  g_ri[idx] = ri;
    g_cr[idx] = 2.f*cmre;          // y_l = cr*s_re + ci*s_im  (= 2*Re(Cm*s))
    g_ci[idx] = -2.f*cmim;
}

// ---------------------------------------------------------------------------
// K1: LayerNorm over H. One warp per (l,b) row (contiguous 512 floats).
// ---------------------------------------------------------------------------
__global__ void ln_kernel(const float* __restrict__ u,
                          const float* __restrict__ lnw,
                          const float* __restrict__ lnb) {
    int warp = (blockIdx.x*blockDim.x + threadIdx.x) >> 5;
    int lane = threadIdx.x & 31;
    if (warp >= L_SEQ*B_SZ) return;
    const float* row = u + (size_t)warp*H_DIM;
    float v[16];
    float s = 0.f, sq = 0.f;
    #pragma unroll
    for (int i = 0; i < 16; i++) {
        float x = row[lane + i*32];
        v[i] = x; s += x; sq += x*x;
    }
    #pragma unroll
    for (int o = 16; o >= 1; o >>= 1) {
        s  += __shfl_xor_sync(0xffffffffu, s,  o);
        sq += __shfl_xor_sync(0xffffffffu, sq, o);
    }
    float mu   = s  * (1.f/H_DIM);
    float var  = sq * (1.f/H_DIM) - mu*mu;
    float rstd = rsqrtf(var + 1e-5f);
    float* orow = g_un + (size_t)warp*H_DIM;
    #pragma unroll
    for (int i = 0; i < 16; i++) {
        int c = lane + i*32;
        orow[c] = (v[i]-mu)*rstd*lnw[c] + lnb[c];
    }
}

// ---------------------------------------------------------------------------
// K2: diagonal-SSM recurrence + D skip + exact GELU.
// One warp per (b,h); lane = state index n (N_HALF == 32).
// Time chunked by 32: lane t preloads u at l0+t, broadcast via shfl.
// ---------------------------------------------------------------------------
__global__ void scan_kernel(const float* __restrict__ D) {
    int warp = (blockIdx.x*blockDim.x + threadIdx.x) >> 5;
    int lane = threadIdx.x & 31;
    if (warp >= BH) return;
    int b = warp / H_DIM;
    int h = warp - b*H_DIM;
    int hi = h*NS + lane;
    float rr = g_rr[hi], ri = g_ri[hi], cr = g_cr[hi], ci = g_ci[hi];
    float Dh = D[h];
    float sre = 0.f, sim = 0.f;
    const float* up = g_un + b*H_DIM + h;          // stride BH over l  (L,B,H)
    float*       yp = g_y + (size_t)warp*L_SEQ;    // (B,H,L) contiguous in l

    float unext = up[(size_t)lane*BH];
    for (int l0 = 0; l0 < L_SEQ; l0 += 32) {
        float uch = unext;
        if (l0 + 32 < L_SEQ) unext = up[(size_t)(l0+32+lane)*BH];
        float yv = 0.f;
        #pragma unroll
        for (int t = 0; t < 32; t++) {
            float uu  = __shfl_sync(0xffffffffu, uch, t);
            float nre = fmaf(rr, sre, fmaf(-ri, sim, uu));
            float nim = fmaf(rr, sim, ri*sre);
            sre = nre; sim = nim;
            float c = fmaf(cr, sre, ci*sim);
            #pragma unroll
            for (int o = 16; o >= 1; o >>= 1)
                c += __shfl_xor_sync(0xffffffffu, c, o);
            if (lane == t) yv = c;
        }
        float yd = yv + Dh*uch;                       // uch is un at this lane's timestep
        float ge = 0.5f*yd*(1.f + erff(yd*0.70710678118f));  // exact GELU
        yp[l0 + lane] = ge;
    }
}

// ---------------------------------------------------------------------------
// K3: fused Conv1d(H->2H,k=1) + GLU + residual + transpose to (L,B,H).
// Per block: 32 h-rows (both a- and g- halves -> 64 W rows) x 64 l-cols, K=512.
// ---------------------------------------------------------------------------
__global__ void gemm_kernel(const float* __restrict__ Wm,
                            const float* __restrict__ bconv,
                            const float* __restrict__ u,
                            float* __restrict__ out) {
    __shared__ float Ws[32][65];    // [k][row(0..63)], pad 65 -> conflict-free
    __shared__ float Ys[32*64];     // [k][l]
    int tid = threadIdx.x;
    int b  = blockIdx.z;
    int h0 = blockIdx.y*32;
    int l0 = blockIdx.x*64;
    int tx = tid & 15, ty = tid >> 4;
    int r0 = ty*2;                  // rows: r0,r0+1 (a) ; r0+32,r0+33 (g)
    float acc[4][4];
    #pragma unroll
    for (int i = 0; i < 4; i++)
        #pragma unroll
        for (int j = 0; j < 4; j++) acc[i][j] = 0.f;

    const float* ybase = g_y + ((size_t)b*H_DIM)*L_SEQ + l0;

    for (int kk = 0; kk < H_DIM; kk += 32) {
        #pragma unroll
        for (int it = 0; it < 8; it++) {            // W tile: 64 rows x 32 k
            int idx = tid + it*256;
            int r = idx >> 5, k = idx & 31;
            int orow = (r < 32) ? (h0 + r) : (H_DIM + h0 + (r - 32));
            Ws[k][r] = Wm[orow*H_DIM + kk + k];
        }
        #pragma unroll
        for (int it = 0; it < 8; it++) {            // Y tile: 32 k x 64 l
            int idx = tid + it*256;
            int k = idx >> 6, c = idx & 63;
            Ys[idx] = ybase[(size_t)(kk + k)*L_SEQ + c];
        }
        __syncthreads();
        #pragma unroll
        for (int k = 0; k < 32; k++) {
            float a0 = Ws[k][r0],    a1 = Ws[k][r0+1];
            float a2 = Ws[k][r0+32], a3 = Ws[k][r0+33];
            float4 bb = reinterpret_cast<const float4*>(Ys + k*64)[tx];
            acc[0][0] = fmaf(a0, bb.x, acc[0][0]);
            acc[0][1] = fmaf(a0, bb.y, acc[0][1]);
            acc[0][2] = fmaf(a0, bb.z, acc[0][2]);
            acc[0][3] = fmaf(a0, bb.w, acc[0][3]);
            acc[1][0] = fmaf(a1, bb.x, acc[1][0]);
            acc[1][1] = fmaf(a1, bb.y, acc[1][1]);
            acc[1][2] = fmaf(a1, bb.z, acc[1][2]);
            acc[1][3] = fmaf(a1, bb.w, acc[1][3]);
            acc[2][0] = fmaf(a2, bb.x, acc[2][0]);
            acc[2][1] = fmaf(a2, bb.y, acc[2][1]);
            acc[2][2] = fmaf(a2, bb.z, acc[2][2]);
            acc[2][3] = fmaf(a2, bb.w, acc[2][3]);
            acc[3][0] = fmaf(a3, bb.x, acc[3][0]);
            acc[3][1] = fmaf(a3, bb.y, acc[3][1]);
            acc[3][2] = fmaf(a3, bb.z, acc[3][2]);
            acc[3][3] = fmaf(a3, bb.w, acc[3][3]);
        }
        __syncthreads();
    }

    int ha0 = h0 + r0, ha1 = h0 + r0 + 1;
    float bA0 = bconv[ha0],       bA1 = bconv[ha1];
    float bG0 = bconv[H_DIM+ha0], bG1 = bconv[H_DIM+ha1];
    #pragma unroll
    for (int j = 0; j < 4; j++) {
        int l = l0 + tx*4 + j;
        size_t base = (size_t)l*BH + (size_t)b*H_DIM;
        float a0v = acc[0][j] + bA0;
        float a1v = acc[1][j] + bA1;
        float g0v = acc[2][j] + bG0;
        float g1v = acc[3][j] + bG1;
        float o0 = a0v * (1.f/(1.f + expf(-g0v)));
        float o1 = a1v * (1.f/(1.f + expf(-g1v)));
        out[base + ha0] = u[base + ha0] + o0;   // residual z = original u
        out[base + ha1] = u[base + ha1] + o1;
    }
}

// ---------------------------------------------------------------------------
extern "C" void kernel_launch(void* const* d_in, const int* in_sizes, int n_in,
                              void* d_out, int out_size) {
    const float* u          = (const float*)d_in[0];
    const float* log_dt     = (const float*)d_in[1];
    const float* C          = (const float*)d_in[2];
    const float* log_A_real = (const float*)d_in[3];
    const float* A_imag     = (const float*)d_in[4];
    const float* D          = (const float*)d_in[5];
    const float* Wm         = (const float*)d_in[6];
    const float* b_conv     = (const float*)d_in[7];
    const float* ln_w       = (const float*)d_in[8];
    const float* ln_b       = (const float*)d_in[9];
    float* out = (float*)d_out;

    const_kernel<<<64, 256>>>(log_dt, C, log_A_real, A_imag);
    ln_kernel<<<(L_SEQ*B_SZ)/8, 256>>>(u, ln_w, ln_b);
    scan_kernel<<<BH/4, 128>>>(D);
    gemm_kernel<<<dim3(L_SEQ/64, H_DIM/32, B_SZ), 256>>>(Wm, b_conv, u, out);
}

// round 6
// speedup vs baseline: 2.3705x; 2.3705x over previous
#include <cuda_runtime.h>
#include <math.h>
#include <stdint.h>

#define L_SEQ 2048
#define B_SZ  16
#define H_DIM 512
#define NS    32
#define BH    (B_SZ*H_DIM)
#define LBH   (L_SEQ*B_SZ*H_DIM)

__device__ float g_un[LBH];            // LN output, (L,B,H)
__device__ float g_yt[LBH];            // gelu output, (B,L,H), tf32-rounded
__device__ float g_wt[2*H_DIM*H_DIM];  // W, tf32-rounded
__device__ float g_rr[H_DIM*NS], g_ri[H_DIM*NS], g_cr[H_DIM*NS], g_ci[H_DIM*NS];

__device__ __forceinline__ uint32_t smem_u32(const void* p) {
    uint32_t a;
    asm("{ .reg .u64 t; cvta.to.shared.u64 t, %1; cvt.u32.u64 %0, t; }" : "=r"(a) : "l"(p));
    return a;
}
__device__ __forceinline__ float to_tf32(float x) {
    uint32_t u;
    asm("cvt.rna.tf32.f32 %0, %1;" : "=r"(u) : "f"(x));
    return __uint_as_float(u);
}

// ---------------- K0: SSM constants ----------------
__global__ void const_kernel(const float* __restrict__ log_dt, const float* __restrict__ C,
                             const float* __restrict__ log_A_real, const float* __restrict__ A_imag) {
    int idx = blockIdx.x*blockDim.x + threadIdx.x;
    if (idx >= H_DIM*NS) return;
    int h = idx >> 5;
    float dt  = expf(log_dt[h]);
    float Are = -expf(log_A_real[idx]);
    float Aim = A_imag[idx];
    float er  = expf(Are*dt);
    float rr  = er*cosf(Aim*dt), ri = er*sinf(Aim*dt);
    float nre = rr - 1.f, nim = ri;
    float den = Are*Are + Aim*Aim;
    float qre = (nre*Are + nim*Aim)/den;
    float qim = (nim*Are - nre*Aim)/den;
    float Cre = C[2*idx], Cim = C[2*idx+1];
    g_rr[idx] = rr;  g_ri[idx] = ri;
    g_cr[idx] = 2.f*(Cre*qre - Cim*qim);
    g_ci[idx] = -2.f*(Cre*qim + Cim*qre);
}

// W -> tf32-rounded copy
__global__ void wcvt_kernel(const float* __restrict__ Wm) {
    int i = blockIdx.x*blockDim.x + threadIdx.x;
    g_wt[i] = to_tf32(Wm[i]);
}

// ---------------- K1: LayerNorm over H, warp per (l,b) ----------------
__global__ void ln_kernel(const float* __restrict__ u, const float* __restrict__ lnw,
                          const float* __restrict__ lnb) {
    int warp = (blockIdx.x*blockDim.x + threadIdx.x) >> 5;
    int lane = threadIdx.x & 31;
    const float* row = u + (size_t)warp*H_DIM;
    float v[16], s = 0.f, sq = 0.f;
    #pragma unroll
    for (int i = 0; i < 16; i++) { float x = row[lane + i*32]; v[i] = x; s += x; sq += x*x; }
    #pragma unroll
    for (int o = 16; o >= 1; o >>= 1) {
        s  += __shfl_xor_sync(0xffffffffu, s,  o);
        sq += __shfl_xor_sync(0xffffffffu, sq, o);
    }
    float mu = s*(1.f/H_DIM);
    float rstd = rsqrtf(sq*(1.f/H_DIM) - mu*mu + 1e-5f);
    float* orow = g_un + (size_t)warp*H_DIM;
    #pragma unroll
    for (int i = 0; i < 16; i++) {
        int c = lane + i*32;
        orow[c] = (v[i]-mu)*rstd*lnw[c] + lnb[c];
    }
}

// ---------------- K2: scan + Dskip + GELU, fused transpose to (B,L,H) -------
// Block 512 thr = 16 warps = 16 h of one b. lane = state n. 32-step chunks,
// log-transpose multi-reduce (31 shfl) instead of per-step butterfly.
__global__ void __launch_bounds__(512) scan_kernel(const float* __restrict__ D) {
    __shared__ float us[32][17], ys[32][17];
    int tid = threadIdx.x, w = tid >> 5, lane = tid & 31;
    int h0 = blockIdx.x*16, b = blockIdx.y;
    int h = h0 + w, hi = h*NS + lane;
    float rr = g_rr[hi], ri = g_ri[hi], cr = g_cr[hi], ci = g_ci[hi];
    float Dh = D[h];
    float sre = 0.f, sim = 0.f;
    int lu = tid >> 4, cu = tid & 15;
    const float* usrc = g_un + (size_t)b*H_DIM + h0;

    for (int l0 = 0; l0 < L_SEQ; l0 += 32) {
        us[lu][cu] = usrc[(size_t)(l0 + lu)*BH + cu];
        __syncthreads();
        float uch = us[lane][w];
        float v[32];
        #pragma unroll
        for (int t = 0; t < 32; t++) {
            float uu  = __shfl_sync(0xffffffffu, uch, t);
            float nre = fmaf(rr, sre, fmaf(-ri, sim, uu));
            float nim = fmaf(rr, sim, ri*sre);
            sre = nre; sim = nim;
            v[t] = fmaf(cr, sre, ci*sim);
        }
        // lane n ends with sum over lanes of v at timestep n
        float t16[16], t8[8], t4[4], t2[2], y;
        { bool hb = lane & 16;
          #pragma unroll
          for (int j = 0; j < 16; j++) {
              float r = __shfl_xor_sync(0xffffffffu, hb ? v[j] : v[j+16], 16);
              t16[j] = (hb ? v[j+16] : v[j]) + r; } }
        { bool hb = lane & 8;
          #pragma unroll
          for (int j = 0; j < 8; j++) {
              float r = __shfl_xor_sync(0xffffffffu, hb ? t16[j] : t16[j+8], 8);
              t8[j] = (hb ? t16[j+8] : t16[j]) + r; } }
        { bool hb = lane & 4;
          #pragma unroll
          for (int j = 0; j < 4; j++) {
              float r = __shfl_xor_sync(0xffffffffu, hb ? t8[j] : t8[j+4], 4);
              t4[j] = (hb ? t8[j+4] : t8[j]) + r; } }
        { bool hb = lane & 2;
          #pragma unroll
          for (int j = 0; j < 2; j++) {
              float r = __shfl_xor_sync(0xffffffffu, hb ? t4[j] : t4[j+2], 2);
              t2[j] = (hb ? t4[j+2] : t4[j]) + r; } }
        { bool hb = lane & 1;
          float r = __shfl_xor_sync(0xffffffffu, hb ? t2[0] : t2[1], 1);
          y = (hb ? t2[1] : t2[0]) + r; }
        float yd = y + Dh*uch;
        float ge = 0.5f*yd*(1.f + erff(yd*0.70710678118f));
        ys[lane][w] = to_tf32(ge);
        __syncthreads();
        g_yt[((size_t)b*L_SEQ + l0 + lu)*H_DIM + h0 + cu] = ys[lu][cu];
    }
}

// ---------------- K3: mma.sync tf32 GEMM + GLU + residual -------------------
// CTA: 128 l x 128 o-cols (even col -> a-row h0+c/2, odd -> g-row 512+h0+c/2),
// K=512 in 16-wide cp.async double-buffered chunks. 8 warps, warp tile 64x32.
#define NKT 32
__global__ void __launch_bounds__(256) mma_gemm(const float* __restrict__ bconv,
                                                const float* __restrict__ u,
                                                float* __restrict__ out) {
    __shared__ float As[2][128][20];   // [buf][l][k(16)+pad4], stride 20 -> conflict-free frags
    __shared__ float Bs[2][128][20];   // [buf][ocol][k]
    int tid = threadIdx.x;
    int l0 = blockIdx.x*128, h0 = blockIdx.y*64, b = blockIdx.z;
    int wid = tid >> 5, lane = tid & 31;
    int wm = wid & 1, wn = wid >> 1;
    int g = lane >> 2, t = lane & 3;
    const float* Abase = g_yt + ((size_t)b*L_SEQ + l0)*H_DIM;

    float c[4][4][4];
    #pragma unroll
    for (int i = 0; i < 4; i++)
        #pragma unroll
        for (int j = 0; j < 4; j++)
            #pragma unroll
            for (int q = 0; q < 4; q++) c[i][j][q] = 0.f;

    auto load_stage = [&](int kt, int buf) {
        int k0 = kt*16;
        #pragma unroll
        for (int p = 0; p < 2; p++) {
            int idx = tid + p*256;          // 0..511
            int r = idx >> 2, seg = idx & 3;
            const float* srcA = Abase + (size_t)r*H_DIM + k0 + seg*4;
            uint32_t dstA = smem_u32(&As[buf][r][seg*4]);
            asm volatile("cp.async.cg.shared.global [%0], [%1], 16;" :: "r"(dstA), "l"(srcA));
            int orow = (r & 1) ? (H_DIM + h0 + (r >> 1)) : (h0 + (r >> 1));
            const float* srcB = g_wt + (size_t)orow*H_DIM + k0 + seg*4;
            uint32_t dstB = smem_u32(&Bs[buf][r][seg*4]);
            asm volatile("cp.async.cg.shared.global [%0], [%1], 16;" :: "r"(dstB), "l"(srcB));
        }
    };
    auto compute = [&](int buf) {
        #pragma unroll
        for (int kk = 0; kk < 16; kk += 8) {
            uint32_t a[4][4], bb[4][2];
            #pragma unroll
            for (int mt = 0; mt < 4; mt++) {
                int m = wm*64 + mt*16 + g;
                a[mt][0] = __float_as_uint(As[buf][m][kk+t]);
                a[mt][1] = __float_as_uint(As[buf][m+8][kk+t]);
                a[mt][2] = __float_as_uint(As[buf][m][kk+t+4]);
                a[mt][3] = __float_as_uint(As[buf][m+8][kk+t+4]);
            }
            #pragma unroll
            for (int nt = 0; nt < 4; nt++) {
                int n = wn*32 + nt*8 + g;
                bb[nt][0] = __float_as_uint(Bs[buf][n][kk+t]);
                bb[nt][1] = __float_as_uint(Bs[buf][n][kk+t+4]);
            }
            #pragma unroll
            for (int mt = 0; mt < 4; mt++)
                #pragma unroll
                for (int nt = 0; nt < 4; nt++)
                    asm volatile(
                        "mma.sync.aligned.m16n8k8.row.col.f32.tf32.tf32.f32 "
                        "{%0,%1,%2,%3}, {%4,%5,%6,%7}, {%8,%9}, {%0,%1,%2,%3};"
                        : "+f"(c[mt][nt][0]), "+f"(c[mt][nt][1]),
                          "+f"(c[mt][nt][2]), "+f"(c[mt][nt][3])
                        : "r"(a[mt][0]), "r"(a[mt][1]), "r"(a[mt][2]), "r"(a[mt][3]),
                          "r"(bb[nt][0]), "r"(bb[nt][1]));
        }
    };

    load_stage(0, 0);
    asm volatile("cp.async.commit_group;");
    for (int kt = 0; kt < NKT; kt++) {
        if (kt + 1 < NKT) {
            load_stage(kt + 1, (kt + 1) & 1);
            asm volatile("cp.async.commit_group;");
            asm volatile("cp.async.wait_group 1;");
        } else {
            asm volatile("cp.async.wait_group 0;");
        }
        __syncthreads();
        compute(kt & 1);
        __syncthreads();
    }

    // Epilogue: c0/c1 = (a,g) at (l, h); c2/c3 at (l+8, h)
    #pragma unroll
    for (int mt = 0; mt < 4; mt++) {
        #pragma unroll
        for (int nt = 0; nt < 4; nt++) {
            int h = h0 + wn*16 + nt*4 + t;
            float bA = bconv[h], bG = bconv[H_DIM + h];
            #pragma unroll
            for (int r2 = 0; r2 < 2; r2++) {
                int l = l0 + wm*64 + mt*16 + g + r2*8;
                float av = c[mt][nt][r2*2+0] + bA;
                float gv = c[mt][nt][r2*2+1] + bG;
                size_t o = (size_t)l*BH + (size_t)b*H_DIM + h;
                out[o] = u[o] + av * (1.f/(1.f + __expf(-gv)));
            }
        }
    }
}

// ---------------------------------------------------------------------------
extern "C" void kernel_launch(void* const* d_in, const int* in_sizes, int n_in,
                              void* d_out, int out_size) {
    const float* u          = (const float*)d_in[0];
    const float* log_dt     = (const float*)d_in[1];
    const float* C          = (const float*)d_in[2];
    const float* log_A_real = (const float*)d_in[3];
    const float* A_imag     = (const float*)d_in[4];
    const float* D          = (const float*)d_in[5];
    const float* Wm         = (const float*)d_in[6];
    const float* b_conv     = (const float*)d_in[7];
    const float* ln_w       = (const float*)d_in[8];
    const float* ln_b       = (const float*)d_in[9];
    float* out = (float*)d_out;

    const_kernel<<<64, 256>>>(log_dt, C, log_A_real, A_imag);
    wcvt_kernel<<<512, 1024>>>(Wm);
    ln_kernel<<<(L_SEQ*B_SZ)/8, 256>>>(u, ln_w, ln_b);
    scan_kernel<<<dim3(H_DIM/16, B_SZ), 512>>>(D);
    mma_gemm<<<dim3(L_SEQ/128, H_DIM/64, B_SZ), 256>>>(b_conv, u, out);
}

// round 8
// speedup vs baseline: 2.4787x; 1.0456x over previous
#include <cuda_runtime.h>
#include <math.h>
#include <stdint.h>

#define L_SEQ 2048
#define B_SZ  16
#define H_DIM 512
#define NS    32
#define BH    (B_SZ*H_DIM)
#define LBH   (L_SEQ*B_SZ*H_DIM)

__device__ float g_un[LBH];            // LN output, (L,B,H)
__device__ float g_yt[LBH];            // gelu output, (B,L,H), tf32-rounded
__device__ float g_wt[2*H_DIM*H_DIM];  // W, tf32-rounded
__device__ float g_rr[H_DIM*NS], g_ri[H_DIM*NS], g_cr[H_DIM*NS], g_ci[H_DIM*NS];

__device__ __forceinline__ uint32_t smem_u32(const void* p) {
    uint32_t a;
    asm("{ .reg .u64 t; cvta.to.shared.u64 t, %1; cvt.u32.u64 %0, t; }" : "=r"(a) : "l"(p));
    return a;
}
__device__ __forceinline__ float to_tf32(float x) {
    uint32_t u;
    asm("cvt.rna.tf32.f32 %0, %1;" : "=r"(u) : "f"(x));
    return __uint_as_float(u);
}

// ---------------- K0: SSM constants ----------------
__global__ void const_kernel(const float* __restrict__ log_dt, const float* __restrict__ C,
                             const float* __restrict__ log_A_real, const float* __restrict__ A_imag) {
    int idx = blockIdx.x*blockDim.x + threadIdx.x;
    if (idx >= H_DIM*NS) return;
    int h = idx >> 5;
    float dt  = expf(log_dt[h]);
    float Are = -expf(log_A_real[idx]);
    float Aim = A_imag[idx];
    float er  = expf(Are*dt);
    float rr  = er*cosf(Aim*dt), ri = er*sinf(Aim*dt);
    float nre = rr - 1.f, nim = ri;
    float den = Are*Are + Aim*Aim;
    float qre = (nre*Are + nim*Aim)/den;
    float qim = (nim*Are - nre*Aim)/den;
    float Cre = C[2*idx], Cim = C[2*idx+1];
    g_rr[idx] = rr;  g_ri[idx] = ri;
    g_cr[idx] = 2.f*(Cre*qre - Cim*qim);
    g_ci[idx] = -2.f*(Cre*qim + Cim*qre);
}

// W -> tf32-rounded copy
__global__ void wcvt_kernel(const float* __restrict__ Wm) {
    int i = blockIdx.x*blockDim.x + threadIdx.x;
    g_wt[i] = to_tf32(Wm[i]);
}

// ---------------- K1: LayerNorm over H, warp per (l,b), float4 -------------
__global__ void ln_kernel(const float* __restrict__ u, const float* __restrict__ lnw,
                          const float* __restrict__ lnb) {
    int warp = (blockIdx.x*blockDim.x + threadIdx.x) >> 5;
    int lane = threadIdx.x & 31;
    const float4* row = (const float4*)(u + (size_t)warp*H_DIM);
    float4 v[4];
    float s = 0.f, sq = 0.f;
    #pragma unroll
    for (int i = 0; i < 4; i++) {
        float4 x = row[lane + i*32];
        v[i] = x;
        s  += x.x + x.y + x.z + x.w;
        sq += x.x*x.x + x.y*x.y + x.z*x.z + x.w*x.w;
    }
    #pragma unroll
    for (int o = 16; o >= 1; o >>= 1) {
        s  += __shfl_xor_sync(0xffffffffu, s,  o);
        sq += __shfl_xor_sync(0xffffffffu, sq, o);
    }
    float mu = s*(1.f/H_DIM);
    float rstd = rsqrtf(sq*(1.f/H_DIM) - mu*mu + 1e-5f);
    float4* orow = (float4*)(g_un + (size_t)warp*H_DIM);
    const float4* w4 = (const float4*)lnw;
    const float4* b4 = (const float4*)lnb;
    #pragma unroll
    for (int i = 0; i < 4; i++) {
        int c = lane + i*32;
        float4 wv = w4[c], bv = b4[c], o;
        o.x = (v[i].x - mu)*rstd*wv.x + bv.x;
        o.y = (v[i].y - mu)*rstd*wv.y + bv.y;
        o.z = (v[i].z - mu)*rstd*wv.z + bv.z;
        o.w = (v[i].w - mu)*rstd*wv.w + bv.w;
        orow[c] = o;
    }
}

// ---------------- K2: scan + Dskip + GELU, fused transpose to (B,L,H) -------
// Block 512 thr = 16 warps = 16 h of one b. lane = state n.
// 2-step-unrolled recurrence: r2 = r^2, (cr1,ci1) = coeffs of c∘r.
//   v[2m]   = cr1*sre + ci1*sim + cr*u0
//   s      <- r2*s + r*u0 + u1
//   v[2m+1] = cr*sre + ci*sim
// u pair fetched via one broadcast LDS.64 from us2[h][t] (t-contiguous).
__global__ void __launch_bounds__(512) scan_kernel(const float* __restrict__ D) {
    __shared__ float us2[16][34];      // [h-local][t], stride 34 (even, padded)
    __shared__ float ys[32][17];
    int tid = threadIdx.x, w = tid >> 5, lane = tid & 31;
    int h0 = blockIdx.x*16, b = blockIdx.y;
    int h = h0 + w, hi = h*NS + lane;
    float rr = g_rr[hi], ri = g_ri[hi], cr = g_cr[hi], ci = g_ci[hi];
    float rr2 = rr*rr - ri*ri, ri2 = 2.f*rr*ri;
    float cr1 = cr*rr + ci*ri, ci1 = ci*rr - cr*ri;
    float Dh = D[h];
    float sre = 0.f, sim = 0.f;
    int hloc = tid & 15, tt = tid >> 4;    // fill mapping: 16 h contiguous per l
    const float* usrc = g_un + (size_t)b*H_DIM + h0;

    for (int l0 = 0; l0 < L_SEQ; l0 += 32) {
        us2[hloc][tt] = usrc[(size_t)(l0 + tt)*BH + hloc];
        __syncthreads();
        float v[32];
        #pragma unroll
        for (int m = 0; m < 16; m++) {
            float2 uu = *(const float2*)&us2[w][2*m];   // broadcast LDS.64
            v[2*m] = fmaf(cr1, sre, fmaf(ci1, sim, cr*uu.x));
            float nre = fmaf(rr2, sre, fmaf(-ri2, sim, fmaf(rr, uu.x, uu.y)));
            float nim = fmaf(rr2, sim, fmaf(ri2, sre, ri*uu.x));
            sre = nre; sim = nim;
            v[2*m+1] = fmaf(cr, sre, ci*sim);
        }
        // butterfly multi-reduce: lane t ends with sum over lanes of v[t]
        float t16[16], t8[8], t4[4], t2[2], y;
        { bool hb = lane & 16;
          #pragma unroll
          for (int j = 0; j < 16; j++) {
              float r = __shfl_xor_sync(0xffffffffu, hb ? v[j] : v[j+16], 16);
              t16[j] = (hb ? v[j+16] : v[j]) + r; } }
        { bool hb = lane & 8;
          #pragma unroll
          for (int j = 0; j < 8; j++) {
              float r = __shfl_xor_sync(0xffffffffu, hb ? t16[j] : t16[j+8], 8);
              t8[j] = (hb ? t16[j+8] : t16[j]) + r; } }
        { bool hb = lane & 4;
          #pragma unroll
          for (int j = 0; j < 4; j++) {
              float r = __shfl_xor_sync(0xffffffffu, hb ? t8[j] : t8[j+4], 4);
              t4[j] = (hb ? t8[j+4] : t8[j]) + r; } }
        { bool hb = lane & 2;
          #pragma unroll
          for (int j = 0; j < 2; j++) {
              float r = __shfl_xor_sync(0xffffffffu, hb ? t4[j] : t4[j+2], 2);
              t2[j] = (hb ? t4[j+2] : t4[j]) + r; } }
        { bool hb = lane & 1;
          float r = __shfl_xor_sync(0xffffffffu, hb ? t2[0] : t2[1], 1);
          y = (hb ? t2[1] : t2[0]) + r; }
        float uch = us2[w][lane];              // u at this lane's timestep
        float yd = y + Dh*uch;
        float ge = 0.5f*yd*(1.f + erff(yd*0.70710678118f));
        ys[lane][w] = to_tf32(ge);
        __syncthreads();
        g_yt[((size_t)b*L_SEQ + l0 + tt)*H_DIM + h0 + hloc] = ys[tt][hloc];
    }
}

// ---------------- K3: mma.sync tf32 GEMM + GLU + residual -------------------
// CTA: 128 l x 128 o-cols (even col -> a-row h0+c/2, odd -> g-row 512+h0+c/2),
// K=512 in 16-wide cp.async double-buffered chunks. 8 warps, warp tile 64x32.
#define NKT 32
__global__ void __launch_bounds__(256) mma_gemm(const float* __restrict__ bconv,
                                                const float* __restrict__ u,
                                                float* __restrict__ out) {
    __shared__ float As[2][128][20];   // [buf][l][k(16)+pad4]
    __shared__ float Bs[2][128][20];   // [buf][ocol][k]
    int tid = threadIdx.x;
    int l0 = blockIdx.x*128, h0 = blockIdx.y*64, b = blockIdx.z;
    int wid = tid >> 5, lane = tid & 31;
    int wm = wid & 1, wn = wid >> 1;
    int g = lane >> 2, t = lane & 3;
    const float* Abase = g_yt + ((size_t)b*L_SEQ + l0)*H_DIM;

    float c[4][4][4];
    #pragma unroll
    for (int i = 0; i < 4; i++)
        #pragma unroll
        for (int j = 0; j < 4; j++)
            #pragma unroll
            for (int q = 0; q < 4; q++) c[i][j][q] = 0.f;

    auto load_stage = [&](int kt, int buf) {
        int k0 = kt*16;
        #pragma unroll
        for (int p = 0; p < 2; p++) {
            int idx = tid + p*256;          // 0..511
            int r = idx >> 2, seg = idx & 3;
            const float* srcA = Abase + (size_t)r*H_DIM + k0 + seg*4;
            uint32_t dstA = smem_u32(&As[buf][r][seg*4]);
            asm volatile("cp.async.cg.shared.global [%0], [%1], 16;" :: "r"(dstA), "l"(srcA));
            int orow = (r & 1) ? (H_DIM + h0 + (r >> 1)) : (h0 + (r >> 1));
            const float* srcB = g_wt + (size_t)orow*H_DIM + k0 + seg*4;
            uint32_t dstB = smem_u32(&Bs[buf][r][seg*4]);
            asm volatile("cp.async.cg.shared.global [%0], [%1], 16;" :: "r"(dstB), "l"(srcB));
        }
    };
    auto compute = [&](int buf) {
        #pragma unroll
        for (int kk = 0; kk < 16; kk += 8) {
            uint32_t a[4][4], bb[4][2];
            #pragma unroll
            for (int mt = 0; mt < 4; mt++) {
                int m = wm*64 + mt*16 + g;
                a[mt][0] = __float_as_uint(As[buf][m][kk+t]);
                a[mt][1] = __float_as_uint(As[buf][m+8][kk+t]);
                a[mt][2] = __float_as_uint(As[buf][m][kk+t+4]);
                a[mt][3] = __float_as_uint(As[buf][m+8][kk+t+4]);
            }
            #pragma unroll
            for (int nt = 0; nt < 4; nt++) {
                int n = wn*32 + nt*8 + g;
                bb[nt][0] = __float_as_uint(Bs[buf][n][kk+t]);
                bb[nt][1] = __float_as_uint(Bs[buf][n][kk+t+4]);
            }
            #pragma unroll
            for (int mt = 0; mt < 4; mt++)
                #pragma unroll
                for (int nt = 0; nt < 4; nt++)
                    asm volatile(
                        "mma.sync.aligned.m16n8k8.row.col.f32.tf32.tf32.f32 "
                        "{%0,%1,%2,%3}, {%4,%5,%6,%7}, {%8,%9}, {%0,%1,%2,%3};"
                        : "+f"(c[mt][nt][0]), "+f"(c[mt][nt][1]),
                          "+f"(c[mt][nt][2]), "+f"(c[mt][nt][3])
                        : "r"(a[mt][0]), "r"(a[mt][1]), "r"(a[mt][2]), "r"(a[mt][3]),
                          "r"(bb[nt][0]), "r"(bb[nt][1]));
        }
    };

    load_stage(0, 0);
    asm volatile("cp.async.commit_group;");
    for (int kt = 0; kt < NKT; kt++) {
        if (kt + 1 < NKT) {
            load_stage(kt + 1, (kt + 1) & 1);
            asm volatile("cp.async.commit_group;");
            asm volatile("cp.async.wait_group 1;");
        } else {
            asm volatile("cp.async.wait_group 0;");
        }
        __syncthreads();
        compute(kt & 1);
        __syncthreads();
    }

    // Epilogue: c0/c1 = (a,g) at (l, h); c2/c3 at (l+8, h)
    #pragma unroll
    for (int mt = 0; mt < 4; mt++) {
        #pragma unroll
        for (int nt = 0; nt < 4; nt++) {
            int h = h0 + wn*16 + nt*4 + t;
            float bA = bconv[h], bG = bconv[H_DIM + h];
            #pragma unroll
            for (int r2 = 0; r2 < 2; r2++) {
                int l = l0 + wm*64 + mt*16 + g + r2*8;
                float av = c[mt][nt][r2*2+0] + bA;
                float gv = c[mt][nt][r2*2+1] + bG;
                size_t o = (size_t)l*BH + (size_t)b*H_DIM + h;
                out[o] = u[o] + av * (1.f/(1.f + __expf(-gv)));
            }
        }
    }
}

// ---------------------------------------------------------------------------
extern "C" void kernel_launch(void* const* d_in, const int* in_sizes, int n_in,
                              void* d_out, int out_size) {
    const float* u          = (const float*)d_in[0];
    const float* log_dt     = (const float*)d_in[1];
    const float* C          = (const float*)d_in[2];
    const float* log_A_real = (const float*)d_in[3];
    const float* A_imag     = (const float*)d_in[4];
    const float* D          = (const float*)d_in[5];
    const float* Wm         = (const float*)d_in[6];
    const float* b_conv     = (const float*)d_in[7];
    const float* ln_w       = (const float*)d_in[8];
    const float* ln_b       = (const float*)d_in[9];
    float* out = (float*)d_out;

    const_kernel<<<64, 256>>>(log_dt, C, log_A_real, A_imag);
    wcvt_kernel<<<512, 1024>>>(Wm);
    ln_kernel<<<(L_SEQ*B_SZ)/8, 256>>>(u, ln_w, ln_b);
    scan_kernel<<<dim3(H_DIM/16, B_SZ), 512>>>(D);
    mma_gemm<<<dim3(L_SEQ/128, H_DIM/64, B_SZ), 256>>>(b_conv, u, out);
}